// round 1
// baseline (speedup 1.0000x reference)
#include <cuda_runtime.h>
#include <math.h>

#define SEQ 8192
#define DM  2048
#define DK  128

// Scratch for projected Q (pre-scaled by 1/sqrt(dk)), K, V  (4 MB each)
__device__ float g_Q[SEQ * DK];
__device__ float g_K[SEQ * DK];
__device__ float g_V[SEQ * DK];

// ---------------------------------------------------------------------------
// Kernel 1: QKV projection.  out[m][n] = (sum_k x[m][k]*W[n][k] + b[n]) * scale
// BM=64, BN=128(=DK), BK=32.  256 threads, each computes 4x8.
// ---------------------------------------------------------------------------
__global__ __launch_bounds__(256) void proj_kernel(
    const float* __restrict__ x,
    const float* __restrict__ Wq, const float* __restrict__ bq,
    const float* __restrict__ Wk, const float* __restrict__ bk,
    const float* __restrict__ Wv, const float* __restrict__ bv)
{
    const int which = blockIdx.y;
    const float* W;
    const float* b;
    float* out;
    float scale;
    if (which == 0)      { W = Wq; b = bq; out = g_Q; scale = 0.08838834764831845f; } // 1/sqrt(128)
    else if (which == 1) { W = Wk; b = bk; out = g_K; scale = 1.0f; }
    else                 { W = Wv; b = bv; out = g_V; scale = 1.0f; }

    __shared__ float Ast[32][68];   // A^T tile: [k][m], m-pad 64->68
    __shared__ float Bst[32][132];  // B^T tile: [k][n], n-pad 128->132

    const int tid = threadIdx.x;
    const int tx = tid & 15;
    const int ty = tid >> 4;
    const int mBase = blockIdx.x * 64;

    float acc[4][8];
#pragma unroll
    for (int i = 0; i < 4; i++)
#pragma unroll
        for (int j = 0; j < 8; j++) acc[i][j] = 0.0f;

    for (int k0 = 0; k0 < DM; k0 += 32) {
        // Load A tile: x[mBase..+63][k0..+31]  (512 float4, 2 per thread)
#pragma unroll
        for (int i = 0; i < 2; i++) {
            int id  = tid + i * 256;        // 0..511
            int row = id >> 3;              // 64 rows, 8 float4 per row
            int c4  = (id & 7) * 4;
            float4 v = *(const float4*)&x[(size_t)(mBase + row) * DM + k0 + c4];
            Ast[c4 + 0][row] = v.x;
            Ast[c4 + 1][row] = v.y;
            Ast[c4 + 2][row] = v.z;
            Ast[c4 + 3][row] = v.w;
        }
        // Load B tile: W[0..127][k0..+31]  (1024 float4, 4 per thread)
#pragma unroll
        for (int i = 0; i < 4; i++) {
            int id  = tid + i * 256;        // 0..1023
            int row = id >> 3;              // 128 rows
            int c4  = (id & 7) * 4;
            float4 v = *(const float4*)&W[(size_t)row * DM + k0 + c4];
            Bst[c4 + 0][row] = v.x;
            Bst[c4 + 1][row] = v.y;
            Bst[c4 + 2][row] = v.z;
            Bst[c4 + 3][row] = v.w;
        }
        __syncthreads();

#pragma unroll 8
        for (int k = 0; k < 32; k++) {
            float4 a0 = *(const float4*)&Ast[k][4 * ty];
            float4 b0 = *(const float4*)&Bst[k][4 * tx];
            float4 b1 = *(const float4*)&Bst[k][64 + 4 * tx];
            float a[4] = {a0.x, a0.y, a0.z, a0.w};
            float bb[8] = {b0.x, b0.y, b0.z, b0.w, b1.x, b1.y, b1.z, b1.w};
#pragma unroll
            for (int i = 0; i < 4; i++)
#pragma unroll
                for (int j = 0; j < 8; j++) acc[i][j] += a[i] * bb[j];
        }
        __syncthreads();
    }

    // Epilogue: bias + scale, write out
#pragma unroll
    for (int i = 0; i < 4; i++) {
        int row = mBase + 4 * ty + i;
#pragma unroll
        for (int jj = 0; jj < 2; jj++) {
            int c = jj * 64 + 4 * tx;
            float4 o;
            o.x = (acc[i][jj * 4 + 0] + b[c + 0]) * scale;
            o.y = (acc[i][jj * 4 + 1] + b[c + 1]) * scale;
            o.z = (acc[i][jj * 4 + 2] + b[c + 2]) * scale;
            o.w = (acc[i][jj * 4 + 3] + b[c + 3]) * scale;
            *(float4*)&out[(size_t)row * DK + c] = o;
        }
    }
}

// ---------------------------------------------------------------------------
// Kernel 2: flash attention, fp32.
// BLOCK_M = 64 queries per CTA, BLOCK_N = 64 keys per tile, D = 128.
// 256 threads (16x16): S micro-tile 4x4, O micro-tile 4x8.
// Dynamic smem:
//   QsT [128][68]  (k-major, transposed)   34816 B
//   KsT [128][68]                          34816 B
//   Vs  [64][128]  (row-major)             32768 B
//   PsT [64][68]   (key-major, transposed) 17408 B
// total 119808 B
// ---------------------------------------------------------------------------
#define QST_STRIDE 68
#define PST_STRIDE 68
#define FLASH_SMEM (128 * 68 * 4 * 2 + 64 * 128 * 4 + 64 * 68 * 4)

__global__ __launch_bounds__(256) void flash_kernel(float* __restrict__ out)
{
    extern __shared__ float smem[];
    float* QsT = smem;                   // [128][68]
    float* KsT = QsT + 128 * QST_STRIDE; // [128][68]
    float* Vs  = KsT + 128 * QST_STRIDE; // [64][128]
    float* PsT = Vs + 64 * 128;          // [64][68]

    const int tid = threadIdx.x;
    const int tx = tid & 15;
    const int ty = tid >> 4;
    const int qBase = blockIdx.x * 64;

    // Load Q tile, transposed: QsT[k][r] = Q[qBase+r][k]
#pragma unroll
    for (int i = 0; i < 8; i++) {
        int id  = tid + i * 256;       // 0..2047
        int row = id >> 5;             // 64 rows, 32 float4 per row
        int c4  = (id & 31) * 4;
        float4 v = *(const float4*)&g_Q[(size_t)(qBase + row) * DK + c4];
        QsT[(c4 + 0) * QST_STRIDE + row] = v.x;
        QsT[(c4 + 1) * QST_STRIDE + row] = v.y;
        QsT[(c4 + 2) * QST_STRIDE + row] = v.z;
        QsT[(c4 + 3) * QST_STRIDE + row] = v.w;
    }

    float m_i[4], l_i[4];
    float O[4][8];
#pragma unroll
    for (int i = 0; i < 4; i++) {
        m_i[i] = -1e30f;
        l_i[i] = 0.0f;
#pragma unroll
        for (int j = 0; j < 8; j++) O[i][j] = 0.0f;
    }

    for (int kt = 0; kt < SEQ / 64; kt++) {
        const int kBase = kt * 64;
        __syncthreads();  // prev PV done: safe to overwrite KsT/Vs

        // Load K tile transposed + V tile row-major (2048 float4 each)
#pragma unroll
        for (int i = 0; i < 8; i++) {
            int id  = tid + i * 256;
            int row = id >> 5;
            int c4  = (id & 31) * 4;
            float4 v = *(const float4*)&g_K[(size_t)(kBase + row) * DK + c4];
            KsT[(c4 + 0) * QST_STRIDE + row] = v.x;
            KsT[(c4 + 1) * QST_STRIDE + row] = v.y;
            KsT[(c4 + 2) * QST_STRIDE + row] = v.z;
            KsT[(c4 + 3) * QST_STRIDE + row] = v.w;
            float4 w = *(const float4*)&g_V[(size_t)(kBase + row) * DK + c4];
            *(float4*)&Vs[row * 128 + c4] = w;
        }
        __syncthreads();

        // S = Q * K^T  (Q already scaled by 1/sqrt(dk))
        float s[4][4];
#pragma unroll
        for (int i = 0; i < 4; i++)
#pragma unroll
            for (int j = 0; j < 4; j++) s[i][j] = 0.0f;

#pragma unroll 4
        for (int k = 0; k < 128; k++) {
            float4 a = *(const float4*)&QsT[k * QST_STRIDE + 4 * ty];
            float4 bv = *(const float4*)&KsT[k * QST_STRIDE + 4 * tx];
            float av[4] = {a.x, a.y, a.z, a.w};
            float bb[4] = {bv.x, bv.y, bv.z, bv.w};
#pragma unroll
            for (int i = 0; i < 4; i++)
#pragma unroll
                for (int j = 0; j < 4; j++) s[i][j] += av[i] * bb[j];
        }

        // Online softmax (rows are shared across the 16 tx lanes; width-16 shfl)
        float alpha[4];
#pragma unroll
        for (int i = 0; i < 4; i++) {
            float mx = fmaxf(fmaxf(s[i][0], s[i][1]), fmaxf(s[i][2], s[i][3]));
#pragma unroll
            for (int off = 8; off > 0; off >>= 1)
                mx = fmaxf(mx, __shfl_xor_sync(0xffffffffu, mx, off, 16));
            float m_new = fmaxf(m_i[i], mx);
            alpha[i] = __expf(m_i[i] - m_new);
            m_i[i] = m_new;

            float rs = 0.0f;
#pragma unroll
            for (int j = 0; j < 4; j++) {
                float p = __expf(s[i][j] - m_new);
                s[i][j] = p;
                rs += p;
            }
#pragma unroll
            for (int off = 8; off > 0; off >>= 1)
                rs += __shfl_xor_sync(0xffffffffu, rs, off, 16);
            l_i[i] = l_i[i] * alpha[i] + rs;
#pragma unroll
            for (int j = 0; j < 8; j++) O[i][j] *= alpha[i];
        }

        // Write P transposed: PsT[c][r]
#pragma unroll
        for (int j = 0; j < 4; j++) {
            float4 pv = make_float4(s[0][j], s[1][j], s[2][j], s[3][j]);
            *(float4*)&PsT[(4 * tx + j) * PST_STRIDE + 4 * ty] = pv;
        }
        __syncthreads();

        // O += P * V
#pragma unroll 4
        for (int k = 0; k < 64; k++) {
            float4 a  = *(const float4*)&PsT[k * PST_STRIDE + 4 * ty];
            float4 b0 = *(const float4*)&Vs[k * 128 + 4 * tx];
            float4 b1 = *(const float4*)&Vs[k * 128 + 64 + 4 * tx];
            float av[4] = {a.x, a.y, a.z, a.w};
            float bb[8] = {b0.x, b0.y, b0.z, b0.w, b1.x, b1.y, b1.z, b1.w};
#pragma unroll
            for (int i = 0; i < 4; i++)
#pragma unroll
                for (int j = 0; j < 8; j++) O[i][j] += av[i] * bb[j];
        }
    }

    // Final normalize + write
#pragma unroll
    for (int i = 0; i < 4; i++) {
        float inv_l = 1.0f / l_i[i];
        int row = qBase + 4 * ty + i;
#pragma unroll
        for (int jj = 0; jj < 2; jj++) {
            int c = jj * 64 + 4 * tx;
            float4 o;
            o.x = O[i][jj * 4 + 0] * inv_l;
            o.y = O[i][jj * 4 + 1] * inv_l;
            o.z = O[i][jj * 4 + 2] * inv_l;
            o.w = O[i][jj * 4 + 3] * inv_l;
            *(float4*)&out[(size_t)row * DK + c] = o;
        }
    }
}

// ---------------------------------------------------------------------------
extern "C" void kernel_launch(void* const* d_in, const int* in_sizes, int n_in,
                              void* d_out, int out_size)
{
    const float* x  = (const float*)d_in[0];
    const float* Wq = (const float*)d_in[1];
    const float* bq = (const float*)d_in[2];
    const float* Wk = (const float*)d_in[3];
    const float* bk = (const float*)d_in[4];
    const float* Wv = (const float*)d_in[5];
    const float* bv = (const float*)d_in[6];
    float* out = (float*)d_out;

    dim3 gProj(SEQ / 64, 3);
    proj_kernel<<<gProj, 256>>>(x, Wq, bq, Wk, bk, Wv, bv);

    cudaFuncSetAttribute(flash_kernel,
                         cudaFuncAttributeMaxDynamicSharedMemorySize, FLASH_SMEM);
    flash_kernel<<<SEQ / 64, 256, FLASH_SMEM>>>(out);
}

// round 4
// speedup vs baseline: 2.6670x; 2.6670x over previous
#include <cuda_runtime.h>
#include <cuda_bf16.h>
#include <stdint.h>

#define SEQ 8192
#define DM  2048
#define DK  128

// Split-precision projected tensors (hi + lo bf16)
__device__ __nv_bfloat16 g_Qh[SEQ * DK], g_Ql[SEQ * DK];
__device__ __nv_bfloat16 g_Kh[SEQ * DK], g_Kl[SEQ * DK];
__device__ __nv_bfloat16 g_Vh[SEQ * DK], g_Vl[SEQ * DK];

// ---------------------------------------------------------------------------
// helpers
// ---------------------------------------------------------------------------
__device__ __forceinline__ uint32_t smem_u32(const void* p) {
    uint32_t a;
    asm("{ .reg .u64 t; cvta.to.shared.u64 t, %1; cvt.u32.u64 %0, t; }" : "=r"(a) : "l"(p));
    return a;
}

// split fp32 pair into packed bf16 hi-pair and lo-pair (low 16 bits = first elem)
__device__ __forceinline__ void split_pair(float a, float b, uint32_t& hi, uint32_t& lo) {
    __nv_bfloat16 ah = __float2bfloat16_rn(a);
    __nv_bfloat16 bh = __float2bfloat16_rn(b);
    float ar = a - __bfloat162float(ah);
    float br = b - __bfloat162float(bh);
    __nv_bfloat16 al = __float2bfloat16_rn(ar);
    __nv_bfloat16 bl = __float2bfloat16_rn(br);
    hi = ((uint32_t)__bfloat16_as_ushort(bh) << 16) | (uint32_t)__bfloat16_as_ushort(ah);
    lo = ((uint32_t)__bfloat16_as_ushort(bl) << 16) | (uint32_t)__bfloat16_as_ushort(al);
}

__device__ __forceinline__ void mma_bf16(float c[4], const uint32_t a[4], const uint32_t b[2]) {
    asm volatile(
        "mma.sync.aligned.m16n8k16.row.col.f32.bf16.bf16.f32 "
        "{%0,%1,%2,%3}, {%4,%5,%6,%7}, {%8,%9}, {%0,%1,%2,%3};"
        : "+f"(c[0]), "+f"(c[1]), "+f"(c[2]), "+f"(c[3])
        : "r"(a[0]), "r"(a[1]), "r"(a[2]), "r"(a[3]), "r"(b[0]), "r"(b[1]));
}

__device__ __forceinline__ void ldsm4(uint32_t r[4], uint32_t addr) {
    asm volatile("ldmatrix.sync.aligned.m8n8.x4.shared.b16 {%0,%1,%2,%3}, [%4];"
                 : "=r"(r[0]), "=r"(r[1]), "=r"(r[2]), "=r"(r[3]) : "r"(addr));
}
__device__ __forceinline__ void ldsm4_t(uint32_t r[4], uint32_t addr) {
    asm volatile("ldmatrix.sync.aligned.m8n8.x4.trans.shared.b16 {%0,%1,%2,%3}, [%4];"
                 : "=r"(r[0]), "=r"(r[1]), "=r"(r[2]), "=r"(r[3]) : "r"(addr));
}

// A-fragment (m16k16, row-major tile in smem, rows = m)
__device__ __forceinline__ void ldsm_a(uint32_t r[4], uint32_t base, int stride,
                                       int m_off, int k_off, int lane) {
    int row = m_off + (lane & 7) + ((lane >> 3) & 1) * 8;
    int kc  = k_off + (lane >> 4) * 8;
    ldsm4(r, base + row * stride + kc * 2);
}
// B-fragments for K-style operand (smem rows = n, cols = k); r[0..1]=ntile0, r[2..3]=ntile1
__device__ __forceinline__ void ldsm_bk(uint32_t r[4], uint32_t base, int stride,
                                        int n_off, int k_off, int lane) {
    int row = n_off + (lane & 7) + (lane >> 4) * 8;
    int kc  = k_off + ((lane >> 3) & 1) * 8;
    ldsm4(r, base + row * stride + kc * 2);
}
// B-fragments for V-style operand (smem rows = k, cols = n, transposed load)
__device__ __forceinline__ void ldsm_bv(uint32_t r[4], uint32_t base, int stride,
                                        int k_off, int n_off, int lane) {
    int row = k_off + (lane & 7) + ((lane >> 3) & 1) * 8;
    int nc  = n_off + (lane >> 4) * 8;
    ldsm4_t(r, base + row * stride + nc * 2);
}

// ---------------------------------------------------------------------------
// Kernel 1: QKV projection.  BM=128, BN=128, K-chunks of 64, double buffered.
// 8 warps: warpM = w>>1 (4), warpN = w&1 (2); warp tile m32 x n64.
// ---------------------------------------------------------------------------
#define PRJ_STR 144
#define PRJ_BUF 73728
#define PRJ_SMEM (2 * PRJ_BUF)
// offsets inside a buffer: AH 0, AL 18432, BH 36864, BL 55296

__global__ __launch_bounds__(256, 1) void proj_kernel(
    const float* __restrict__ x,
    const float* __restrict__ Wq, const float* __restrict__ bq,
    const float* __restrict__ Wk, const float* __restrict__ bk,
    const float* __restrict__ Wv, const float* __restrict__ bv)
{
    extern __shared__ char sm[];
    const uint32_t sb = smem_u32(sm);
    const int tid = threadIdx.x;
    const int lane = tid & 31, w = tid >> 5;
    const int warpM = w >> 1, warpN = w & 1;
    const int qr = lane >> 2, q4 = lane & 3;
    const int which = blockIdx.y;
    const float* W    = (which == 0) ? Wq : (which == 1) ? Wk : Wv;
    const float* bias = (which == 0) ? bq : (which == 1) ? bk : bv;
    const int mBase = blockIdx.x * 128;

    float acc[2][8][4];
#pragma unroll
    for (int i = 0; i < 2; i++)
#pragma unroll
        for (int j = 0; j < 8; j++)
#pragma unroll
            for (int c = 0; c < 4; c++) acc[i][j][c] = 0.0f;

    uint4 xa[8], wb[8];
    auto load_regs = [&](int c) {
#pragma unroll
        for (int i = 0; i < 8; i++) {
            int id = tid + i * 256;
            int row = id >> 4, f4 = id & 15;
            xa[i] = *(const uint4*)&x[(size_t)(mBase + row) * DM + c * 64 + f4 * 4];
            wb[i] = *(const uint4*)&W[(size_t)row * DM + c * 64 + f4 * 4];
        }
    };
    auto store_regs = [&](int buf) {
        char* base = sm + buf * PRJ_BUF;
#pragma unroll
        for (int i = 0; i < 8; i++) {
            int id = tid + i * 256;
            int row = id >> 4, f4 = id & 15;
            uint32_t off = (uint32_t)(row * PRJ_STR + f4 * 8);
            uint32_t h0, l0, h1, l1;
            const float4 vx = *(const float4*)&xa[i];
            split_pair(vx.x, vx.y, h0, l0);
            split_pair(vx.z, vx.w, h1, l1);
            *(uint2*)(base + off)         = make_uint2(h0, h1);
            *(uint2*)(base + 18432 + off) = make_uint2(l0, l1);
            const float4 vw = *(const float4*)&wb[i];
            split_pair(vw.x, vw.y, h0, l0);
            split_pair(vw.z, vw.w, h1, l1);
            *(uint2*)(base + 36864 + off) = make_uint2(h0, h1);
            *(uint2*)(base + 55296 + off) = make_uint2(l0, l1);
        }
    };

    load_regs(0);
    store_regs(0);

    const int NCH = DM / 64;  // 32
    for (int c = 0; c < NCH; c++) {
        __syncthreads();
        const int buf = c & 1;
        if (c + 1 < NCH) load_regs(c + 1);

        const uint32_t AH = sb + buf * PRJ_BUF;
        const uint32_t AL = AH + 18432;
        const uint32_t BH = AH + 36864;
        const uint32_t BL = AH + 55296;
#pragma unroll
        for (int kk = 0; kk < 4; kk++) {
            uint32_t ah[2][4], al[2][4];
#pragma unroll
            for (int mt = 0; mt < 2; mt++) {
                ldsm_a(ah[mt], AH, PRJ_STR, warpM * 32 + mt * 16, kk * 16, lane);
                ldsm_a(al[mt], AL, PRJ_STR, warpM * 32 + mt * 16, kk * 16, lane);
            }
            uint32_t bh[4][4], bl[4][4];  // [npair][4] -> ntiles 2p,2p+1
#pragma unroll
            for (int np = 0; np < 4; np++) {
                ldsm_bk(bh[np], BH, PRJ_STR, warpN * 64 + np * 16, kk * 16, lane);
                ldsm_bk(bl[np], BL, PRJ_STR, warpN * 64 + np * 16, kk * 16, lane);
            }
#pragma unroll
            for (int mt = 0; mt < 2; mt++)
#pragma unroll
                for (int nt = 0; nt < 8; nt++) {
                    const uint32_t* bhp = &bh[nt >> 1][(nt & 1) * 2];
                    const uint32_t* blp = &bl[nt >> 1][(nt & 1) * 2];
                    mma_bf16(acc[mt][nt], ah[mt], bhp);
                    mma_bf16(acc[mt][nt], ah[mt], blp);
                    mma_bf16(acc[mt][nt], al[mt], bhp);
                }
        }
        if (c + 1 < NCH) store_regs(1 - buf);
    }

    // Epilogue: bias + scale, split, write
    const float scale = (which == 0) ? 0.08838834764831845f : 1.0f;  // 1/sqrt(128)
    __nv_bfloat16* oh = (which == 0) ? g_Qh : (which == 1) ? g_Kh : g_Vh;
    __nv_bfloat16* ol = (which == 0) ? g_Ql : (which == 1) ? g_Kl : g_Vl;
#pragma unroll
    for (int mt = 0; mt < 2; mt++)
#pragma unroll
        for (int h = 0; h < 2; h++) {
            int row = mBase + warpM * 32 + mt * 16 + qr + h * 8;
#pragma unroll
            for (int nt = 0; nt < 8; nt++) {
                int col = warpN * 64 + nt * 8 + q4 * 2;
                float v0 = (acc[mt][nt][h * 2 + 0] + bias[col]) * scale;
                float v1 = (acc[mt][nt][h * 2 + 1] + bias[col + 1]) * scale;
                uint32_t hi, lo;
                split_pair(v0, v1, hi, lo);
                *(uint32_t*)&oh[(size_t)row * DK + col] = hi;
                *(uint32_t*)&ol[(size_t)row * DK + col] = lo;
            }
        }
}

// ---------------------------------------------------------------------------
// Kernel 2: flash attention.  BM=64, BN=128, D=128.  grid 128, 256 threads.
// 8 warps: warpM = w>>2 (2), warpN = w&3 (4).  Warp: S m32 x n32, O m32 x d128
// over its 32-key slice; O summed across warpN groups at the end.
// smem: redMax[4*64] @0, redSum @1024, linv @2048,
//   QH 4096, QL 21504, KH 38912, KL 73728, VH 108544, VL 143360  (stride 272)
//   O staging aliases KH (64 x 132 f32)
// ---------------------------------------------------------------------------
#define ATT_STR 272
#define AQH 4096
#define AQL 21504
#define AKH 38912
#define AKL 73728
#define AVH 108544
#define AVL 143360
#define ATT_SMEM 178176

__global__ __launch_bounds__(256, 1) void attn_kernel(float* __restrict__ out)
{
    extern __shared__ char sm[];
    const uint32_t sb = smem_u32(sm);
    float* redMax = (float*)(sm);          // [4][64]
    float* redSum = (float*)(sm + 1024);   // [4][64]
    float* linv   = (float*)(sm + 2048);   // [64]
    const int tid = threadIdx.x;
    const int lane = tid & 31, w = tid >> 5;
    const int warpM = w >> 2, warpN = w & 3;
    const int qr = lane >> 2, q4 = lane & 3;
    const int qBase = blockIdx.x * 64;

    // load Q tile (hi+lo): 64 rows x 16 uint4 each
#pragma unroll
    for (int i = 0; i < 4; i++) {
        int id = tid + i * 256;
        int row = id >> 4, c4 = id & 15;
        uint32_t so = (uint32_t)(row * ATT_STR + c4 * 16);
        *(uint4*)(sm + AQH + so) = ((const uint4*)g_Qh)[(size_t)(qBase + row) * 16 + c4];
        *(uint4*)(sm + AQL + so) = ((const uint4*)g_Ql)[(size_t)(qBase + row) * 16 + c4];
    }

    float m_i[2][2], l_i[2][2];
    float o[2][16][4];
#pragma unroll
    for (int mt = 0; mt < 2; mt++)
#pragma unroll
        for (int h = 0; h < 2; h++) { m_i[mt][h] = -1e30f; l_i[mt][h] = 0.0f; }
#pragma unroll
    for (int mt = 0; mt < 2; mt++)
#pragma unroll
        for (int dt = 0; dt < 16; dt++)
#pragma unroll
            for (int c = 0; c < 4; c++) o[mt][dt][c] = 0.0f;

    for (int kt = 0; kt < SEQ / 128; kt++) {
        const int j0 = kt * 128;
        __syncthreads();  // previous iteration's smem reads complete
        // load K/V tiles (hi+lo): 128 rows x 16 uint4 each tensor
#pragma unroll
        for (int i = 0; i < 8; i++) {
            int id = tid + i * 256;
            int row = id >> 4, c4 = id & 15;
            uint32_t so = (uint32_t)(row * ATT_STR + c4 * 16);
            size_t go = (size_t)(j0 + row) * 16 + c4;
            *(uint4*)(sm + AKH + so) = ((const uint4*)g_Kh)[go];
            *(uint4*)(sm + AKL + so) = ((const uint4*)g_Kl)[go];
            *(uint4*)(sm + AVH + so) = ((const uint4*)g_Vh)[go];
            *(uint4*)(sm + AVL + so) = ((const uint4*)g_Vl)[go];
        }
        __syncthreads();

        // ---- S = Q K^T over this warp's n32 slice ----
        float s[2][4][4];
#pragma unroll
        for (int mt = 0; mt < 2; mt++)
#pragma unroll
            for (int nt = 0; nt < 4; nt++)
#pragma unroll
                for (int c = 0; c < 4; c++) s[mt][nt][c] = 0.0f;

#pragma unroll
        for (int kk = 0; kk < 8; kk++) {
            uint32_t ah[2][4], al[2][4];
#pragma unroll
            for (int mt = 0; mt < 2; mt++) {
                ldsm_a(ah[mt], sb + AQH, ATT_STR, warpM * 32 + mt * 16, kk * 16, lane);
                ldsm_a(al[mt], sb + AQL, ATT_STR, warpM * 32 + mt * 16, kk * 16, lane);
            }
            uint32_t bh[2][4], bl[2][4];
#pragma unroll
            for (int np = 0; np < 2; np++) {
                ldsm_bk(bh[np], sb + AKH, ATT_STR, warpN * 32 + np * 16, kk * 16, lane);
                ldsm_bk(bl[np], sb + AKL, ATT_STR, warpN * 32 + np * 16, kk * 16, lane);
            }
#pragma unroll
            for (int mt = 0; mt < 2; mt++)
#pragma unroll
                for (int nt = 0; nt < 4; nt++) {
                    const uint32_t* bhp = &bh[nt >> 1][(nt & 1) * 2];
                    const uint32_t* blp = &bl[nt >> 1][(nt & 1) * 2];
                    mma_bf16(s[mt][nt], ah[mt], bhp);
                    mma_bf16(s[mt][nt], ah[mt], blp);
                    mma_bf16(s[mt][nt], al[mt], bhp);
                }
        }

        // ---- online softmax ----
        float rmax[2][2];
#pragma unroll
        for (int mt = 0; mt < 2; mt++)
#pragma unroll
            for (int h = 0; h < 2; h++) {
                float m = -1e30f;
#pragma unroll
                for (int nt = 0; nt < 4; nt++)
                    m = fmaxf(m, fmaxf(s[mt][nt][h * 2], s[mt][nt][h * 2 + 1]));
                m = fmaxf(m, __shfl_xor_sync(0xffffffffu, m, 1));
                m = fmaxf(m, __shfl_xor_sync(0xffffffffu, m, 2));
                rmax[mt][h] = m;
            }
        if (q4 == 0) {
#pragma unroll
            for (int mt = 0; mt < 2; mt++)
#pragma unroll
                for (int h = 0; h < 2; h++)
                    redMax[warpN * 64 + warpM * 32 + mt * 16 + qr + h * 8] = rmax[mt][h];
        }
        __syncthreads();

        float alpha[2][2];
#pragma unroll
        for (int mt = 0; mt < 2; mt++)
#pragma unroll
            for (int h = 0; h < 2; h++) {
                int R = warpM * 32 + mt * 16 + qr + h * 8;
                float mn = fmaxf(fmaxf(redMax[R], redMax[64 + R]),
                                 fmaxf(redMax[128 + R], redMax[192 + R]));
                mn = fmaxf(m_i[mt][h], mn);
                alpha[mt][h] = __expf(m_i[mt][h] - mn);
                m_i[mt][h] = mn;
                float rs = 0.0f;
#pragma unroll
                for (int nt = 0; nt < 4; nt++) {
                    float p0 = __expf(s[mt][nt][h * 2]     - mn);
                    float p1 = __expf(s[mt][nt][h * 2 + 1] - mn);
                    s[mt][nt][h * 2]     = p0;
                    s[mt][nt][h * 2 + 1] = p1;
                    rs += p0 + p1;
                }
                rs += __shfl_xor_sync(0xffffffffu, rs, 1);
                rs += __shfl_xor_sync(0xffffffffu, rs, 2);
                if (q4 == 0) redSum[warpN * 64 + R] = rs;
            }
        __syncthreads();
#pragma unroll
        for (int mt = 0; mt < 2; mt++)
#pragma unroll
            for (int h = 0; h < 2; h++) {
                int R = warpM * 32 + mt * 16 + qr + h * 8;
                float rs = redSum[R] + redSum[64 + R] + redSum[128 + R] + redSum[192 + R];
                l_i[mt][h] = l_i[mt][h] * alpha[mt][h] + rs;
            }
        // rescale O
#pragma unroll
        for (int mt = 0; mt < 2; mt++)
#pragma unroll
            for (int dt = 0; dt < 16; dt++) {
                o[mt][dt][0] *= alpha[mt][0];
                o[mt][dt][1] *= alpha[mt][0];
                o[mt][dt][2] *= alpha[mt][1];
                o[mt][dt][3] *= alpha[mt][1];
            }

        // ---- PV over this warp's 32-key slice ----
#pragma unroll
        for (int ks = 0; ks < 2; ks++) {
            uint32_t ph[2][4], pl[2][4];
#pragma unroll
            for (int mt = 0; mt < 2; mt++) {
                split_pair(s[mt][2 * ks][0], s[mt][2 * ks][1], ph[mt][0], pl[mt][0]);
                split_pair(s[mt][2 * ks][2], s[mt][2 * ks][3], ph[mt][1], pl[mt][1]);
                split_pair(s[mt][2 * ks + 1][0], s[mt][2 * ks + 1][1], ph[mt][2], pl[mt][2]);
                split_pair(s[mt][2 * ks + 1][2], s[mt][2 * ks + 1][3], ph[mt][3], pl[mt][3]);
            }
            const int k_off = warpN * 32 + ks * 16;
#pragma unroll
            for (int dp = 0; dp < 8; dp++) {
                uint32_t bvh[4], bvl[4];
                ldsm_bv(bvh, sb + AVH, ATT_STR, k_off, dp * 16, lane);
                ldsm_bv(bvl, sb + AVL, ATT_STR, k_off, dp * 16, lane);
#pragma unroll
                for (int mt = 0; mt < 2; mt++)
#pragma unroll
                    for (int j = 0; j < 2; j++) {
                        mma_bf16(o[mt][2 * dp + j], ph[mt], &bvh[j * 2]);
                        mma_bf16(o[mt][2 * dp + j], ph[mt], &bvl[j * 2]);
                        mma_bf16(o[mt][2 * dp + j], pl[mt], &bvh[j * 2]);
                    }
            }
        }
    }

    // ---- reduce O across the 4 warpN groups via staging (aliases K tile) ----
    float* stage = (float*)(sm + AKH);  // [64][132]
    if (warpN == 0 && q4 == 0) {
#pragma unroll
        for (int mt = 0; mt < 2; mt++)
#pragma unroll
            for (int h = 0; h < 2; h++)
                linv[warpM * 32 + mt * 16 + qr + h * 8] = 1.0f / l_i[mt][h];
    }
    for (int wn = 0; wn < 4; wn++) {
        __syncthreads();
        if (warpN == wn) {
#pragma unroll
            for (int mt = 0; mt < 2; mt++)
#pragma unroll
                for (int h = 0; h < 2; h++) {
                    int R = warpM * 32 + mt * 16 + qr + h * 8;
#pragma unroll
                    for (int dt = 0; dt < 16; dt++) {
                        int col = dt * 8 + q4 * 2;
                        if (wn == 0) {
                            stage[R * 132 + col]     = o[mt][dt][h * 2];
                            stage[R * 132 + col + 1] = o[mt][dt][h * 2 + 1];
                        } else {
                            stage[R * 132 + col]     += o[mt][dt][h * 2];
                            stage[R * 132 + col + 1] += o[mt][dt][h * 2 + 1];
                        }
                    }
                }
        }
    }
    __syncthreads();

    // normalize + write
    {
        int row = tid >> 2;
        int cg = (tid & 3) * 32;
        float il = linv[row];
#pragma unroll
        for (int i = 0; i < 8; i++) {
            int col = cg + i * 4;
            float4 v = *(float4*)&stage[row * 132 + col];
            v.x *= il; v.y *= il; v.z *= il; v.w *= il;
            *(float4*)&out[(size_t)(qBase + row) * DK + col] = v;
        }
    }
}

// ---------------------------------------------------------------------------
extern "C" void kernel_launch(void* const* d_in, const int* in_sizes, int n_in,
                              void* d_out, int out_size)
{
    const float* x  = (const float*)d_in[0];
    const float* Wq = (const float*)d_in[1];
    const float* bq = (const float*)d_in[2];
    const float* Wk = (const float*)d_in[3];
    const float* bk = (const float*)d_in[4];
    const float* Wv = (const float*)d_in[5];
    const float* bv = (const float*)d_in[6];
    float* out = (float*)d_out;

    cudaFuncSetAttribute(proj_kernel, cudaFuncAttributeMaxDynamicSharedMemorySize, PRJ_SMEM);
    cudaFuncSetAttribute(attn_kernel, cudaFuncAttributeMaxDynamicSharedMemorySize, ATT_SMEM);

    dim3 gProj(SEQ / 128, 3);
    proj_kernel<<<gProj, 256, PRJ_SMEM>>>(x, Wq, bq, Wk, bk, Wv, bv);
    attn_kernel<<<SEQ / 64, 256, ATT_SMEM>>>(out);
}

// round 5
// speedup vs baseline: 2.6744x; 1.0028x over previous
#include <cuda_runtime.h>
#include <cuda_bf16.h>
#include <stdint.h>

#define SEQ 8192
#define DM  2048
#define DK  128

// Split-precision projected tensors (hi + lo bf16)
__device__ __nv_bfloat16 g_Qh[SEQ * DK], g_Ql[SEQ * DK];
__device__ __nv_bfloat16 g_Kh[SEQ * DK], g_Kl[SEQ * DK];
__device__ __nv_bfloat16 g_Vh[SEQ * DK], g_Vl[SEQ * DK];

// ---------------------------------------------------------------------------
// helpers
// ---------------------------------------------------------------------------
__device__ __forceinline__ uint32_t smem_u32(const void* p) {
    uint32_t a;
    asm("{ .reg .u64 t; cvta.to.shared.u64 t, %1; cvt.u32.u64 %0, t; }" : "=r"(a) : "l"(p));
    return a;
}

// split fp32 pair into packed bf16 hi-pair and lo-pair (low 16 bits = first elem)
__device__ __forceinline__ void split_pair(float a, float b, uint32_t& hi, uint32_t& lo) {
    __nv_bfloat16 ah = __float2bfloat16_rn(a);
    __nv_bfloat16 bh = __float2bfloat16_rn(b);
    float ar = a - __bfloat162float(ah);
    float br = b - __bfloat162float(bh);
    __nv_bfloat16 al = __float2bfloat16_rn(ar);
    __nv_bfloat16 bl = __float2bfloat16_rn(br);
    hi = ((uint32_t)__bfloat16_as_ushort(bh) << 16) | (uint32_t)__bfloat16_as_ushort(ah);
    lo = ((uint32_t)__bfloat16_as_ushort(bl) << 16) | (uint32_t)__bfloat16_as_ushort(al);
}

__device__ __forceinline__ void mma_bf16(float c[4], const uint32_t a[4], const uint32_t b[2]) {
    asm volatile(
        "mma.sync.aligned.m16n8k16.row.col.f32.bf16.bf16.f32 "
        "{%0,%1,%2,%3}, {%4,%5,%6,%7}, {%8,%9}, {%0,%1,%2,%3};"
        : "+f"(c[0]), "+f"(c[1]), "+f"(c[2]), "+f"(c[3])
        : "r"(a[0]), "r"(a[1]), "r"(a[2]), "r"(a[3]), "r"(b[0]), "r"(b[1]));
}

__device__ __forceinline__ void ldsm4(uint32_t r[4], uint32_t addr) {
    asm volatile("ldmatrix.sync.aligned.m8n8.x4.shared.b16 {%0,%1,%2,%3}, [%4];"
                 : "=r"(r[0]), "=r"(r[1]), "=r"(r[2]), "=r"(r[3]) : "r"(addr));
}
__device__ __forceinline__ void ldsm4_t(uint32_t r[4], uint32_t addr) {
    asm volatile("ldmatrix.sync.aligned.m8n8.x4.trans.shared.b16 {%0,%1,%2,%3}, [%4];"
                 : "=r"(r[0]), "=r"(r[1]), "=r"(r[2]), "=r"(r[3]) : "r"(addr));
}

// A-fragment (m16k16, row-major tile in smem, rows = m)
__device__ __forceinline__ void ldsm_a(uint32_t r[4], uint32_t base, int stride,
                                       int m_off, int k_off, int lane) {
    int row = m_off + (lane & 7) + ((lane >> 3) & 1) * 8;
    int kc  = k_off + (lane >> 4) * 8;
    ldsm4(r, base + row * stride + kc * 2);
}
// B-fragments for K-style operand (smem rows = n, cols = k); r[0..1]=ntile0, r[2..3]=ntile1
__device__ __forceinline__ void ldsm_bk(uint32_t r[4], uint32_t base, int stride,
                                        int n_off, int k_off, int lane) {
    int row = n_off + (lane & 7) + (lane >> 4) * 8;
    int kc  = k_off + ((lane >> 3) & 1) * 8;
    ldsm4(r, base + row * stride + kc * 2);
}
// B-fragments for V-style operand (smem rows = k, cols = n, transposed load)
__device__ __forceinline__ void ldsm_bv(uint32_t r[4], uint32_t base, int stride,
                                        int k_off, int n_off, int lane) {
    int row = k_off + (lane & 7) + ((lane >> 3) & 1) * 8;
    int nc  = n_off + (lane >> 4) * 8;
    ldsm4_t(r, base + row * stride + nc * 2);
}

// ---------------------------------------------------------------------------
// Kernel 1: QKV projection.  BM=128, BN=128, K-chunks of 64, double buffered.
// 8 warps: warpM = w>>1 (4), warpN = w&1 (2); warp tile m32 x n64.
// ---------------------------------------------------------------------------
#define PRJ_STR 144
#define PRJ_BUF 73728
#define PRJ_SMEM (2 * PRJ_BUF)
// offsets inside a buffer: AH 0, AL 18432, BH 36864, BL 55296

__global__ __launch_bounds__(256, 1) void proj_kernel(
    const float* __restrict__ x,
    const float* __restrict__ Wq, const float* __restrict__ bq,
    const float* __restrict__ Wk, const float* __restrict__ bk,
    const float* __restrict__ Wv, const float* __restrict__ bv)
{
    extern __shared__ char sm[];
    const uint32_t sb = smem_u32(sm);
    const int tid = threadIdx.x;
    const int lane = tid & 31, w = tid >> 5;
    const int warpM = w >> 1, warpN = w & 1;
    const int qr = lane >> 2, q4 = lane & 3;
    const int which = blockIdx.y;
    const float* W    = (which == 0) ? Wq : (which == 1) ? Wk : Wv;
    const float* bias = (which == 0) ? bq : (which == 1) ? bk : bv;
    const int mBase = blockIdx.x * 128;

    float acc[2][8][4];
#pragma unroll
    for (int i = 0; i < 2; i++)
#pragma unroll
        for (int j = 0; j < 8; j++)
#pragma unroll
            for (int c = 0; c < 4; c++) acc[i][j][c] = 0.0f;

    uint4 xa[8], wb[8];
    auto load_regs = [&](int c) {
#pragma unroll
        for (int i = 0; i < 8; i++) {
            int id = tid + i * 256;
            int row = id >> 4, f4 = id & 15;
            xa[i] = *(const uint4*)&x[(size_t)(mBase + row) * DM + c * 64 + f4 * 4];
            wb[i] = *(const uint4*)&W[(size_t)row * DM + c * 64 + f4 * 4];
        }
    };
    auto store_regs = [&](int buf) {
        char* base = sm + buf * PRJ_BUF;
#pragma unroll
        for (int i = 0; i < 8; i++) {
            int id = tid + i * 256;
            int row = id >> 4, f4 = id & 15;
            uint32_t off = (uint32_t)(row * PRJ_STR + f4 * 8);
            uint32_t h0, l0, h1, l1;
            const float4 vx = *(const float4*)&xa[i];
            split_pair(vx.x, vx.y, h0, l0);
            split_pair(vx.z, vx.w, h1, l1);
            *(uint2*)(base + off)         = make_uint2(h0, h1);
            *(uint2*)(base + 18432 + off) = make_uint2(l0, l1);
            const float4 vw = *(const float4*)&wb[i];
            split_pair(vw.x, vw.y, h0, l0);
            split_pair(vw.z, vw.w, h1, l1);
            *(uint2*)(base + 36864 + off) = make_uint2(h0, h1);
            *(uint2*)(base + 55296 + off) = make_uint2(l0, l1);
        }
    };

    load_regs(0);
    store_regs(0);

    const int NCH = DM / 64;  // 32
    for (int c = 0; c < NCH; c++) {
        __syncthreads();
        const int buf = c & 1;
        if (c + 1 < NCH) load_regs(c + 1);

        const uint32_t AH = sb + buf * PRJ_BUF;
        const uint32_t AL = AH + 18432;
        const uint32_t BH = AH + 36864;
        const uint32_t BL = AH + 55296;
#pragma unroll
        for (int kk = 0; kk < 4; kk++) {
            uint32_t ah[2][4], al[2][4];
#pragma unroll
            for (int mt = 0; mt < 2; mt++) {
                ldsm_a(ah[mt], AH, PRJ_STR, warpM * 32 + mt * 16, kk * 16, lane);
                ldsm_a(al[mt], AL, PRJ_STR, warpM * 32 + mt * 16, kk * 16, lane);
            }
            uint32_t bh[4][4], bl[4][4];  // [npair][4] -> ntiles 2p,2p+1
#pragma unroll
            for (int np = 0; np < 4; np++) {
                ldsm_bk(bh[np], BH, PRJ_STR, warpN * 64 + np * 16, kk * 16, lane);
                ldsm_bk(bl[np], BL, PRJ_STR, warpN * 64 + np * 16, kk * 16, lane);
            }
#pragma unroll
            for (int mt = 0; mt < 2; mt++)
#pragma unroll
                for (int nt = 0; nt < 8; nt++) {
                    const uint32_t* bhp = &bh[nt >> 1][(nt & 1) * 2];
                    const uint32_t* blp = &bl[nt >> 1][(nt & 1) * 2];
                    mma_bf16(acc[mt][nt], ah[mt], bhp);
                    mma_bf16(acc[mt][nt], ah[mt], blp);
                    mma_bf16(acc[mt][nt], al[mt], bhp);
                }
        }
        if (c + 1 < NCH) store_regs(1 - buf);
    }

    // Epilogue: bias + scale, split, write
    const float scale = (which == 0) ? 0.08838834764831845f : 1.0f;  // 1/sqrt(128)
    __nv_bfloat16* oh = (which == 0) ? g_Qh : (which == 1) ? g_Kh : g_Vh;
    __nv_bfloat16* ol = (which == 0) ? g_Ql : (which == 1) ? g_Kl : g_Vl;
#pragma unroll
    for (int mt = 0; mt < 2; mt++)
#pragma unroll
        for (int h = 0; h < 2; h++) {
            int row = mBase + warpM * 32 + mt * 16 + qr + h * 8;
#pragma unroll
            for (int nt = 0; nt < 8; nt++) {
                int col = warpN * 64 + nt * 8 + q4 * 2;
                float v0 = (acc[mt][nt][h * 2 + 0] + bias[col]) * scale;
                float v1 = (acc[mt][nt][h * 2 + 1] + bias[col + 1]) * scale;
                uint32_t hi, lo;
                split_pair(v0, v1, hi, lo);
                *(uint32_t*)&oh[(size_t)row * DK + col] = hi;
                *(uint32_t*)&ol[(size_t)row * DK + col] = lo;
            }
        }
}

// ---------------------------------------------------------------------------
// Kernel 2: flash attention.  BM=64, BN=128, D=128.  grid 128, 256 threads.
// 8 warps: warpM = w>>2 (2), warpN = w&3 (4).  Warp: S m32 x n32, O m32 x d128
// over its 32-key slice; O summed across warpN groups at the end.
// smem: redMax[4*64] @0, redSum @1024, linv @2048,
//   QH 4096, QL 21504, KH 38912, KL 73728, VH 108544, VL 143360  (stride 272)
//   O staging aliases KH (64 x 132 f32)
// ---------------------------------------------------------------------------
#define ATT_STR 272
#define AQH 4096
#define AQL 21504
#define AKH 38912
#define AKL 73728
#define AVH 108544
#define AVL 143360
#define ATT_SMEM 178176

__global__ __launch_bounds__(256, 1) void attn_kernel(float* __restrict__ out)
{
    extern __shared__ char sm[];
    const uint32_t sb = smem_u32(sm);
    float* redMax = (float*)(sm);          // [4][64]
    float* redSum = (float*)(sm + 1024);   // [4][64]
    float* linv   = (float*)(sm + 2048);   // [64]
    const int tid = threadIdx.x;
    const int lane = tid & 31, w = tid >> 5;
    const int warpM = w >> 2, warpN = w & 3;
    const int qr = lane >> 2, q4 = lane & 3;
    const int qBase = blockIdx.x * 64;

    // load Q tile (hi+lo): 64 rows x 16 uint4 each
#pragma unroll
    for (int i = 0; i < 4; i++) {
        int id = tid + i * 256;
        int row = id >> 4, c4 = id & 15;
        uint32_t so = (uint32_t)(row * ATT_STR + c4 * 16);
        *(uint4*)(sm + AQH + so) = ((const uint4*)g_Qh)[(size_t)(qBase + row) * 16 + c4];
        *(uint4*)(sm + AQL + so) = ((const uint4*)g_Ql)[(size_t)(qBase + row) * 16 + c4];
    }

    float m_i[2][2], l_i[2][2];
    float o[2][16][4];
#pragma unroll
    for (int mt = 0; mt < 2; mt++)
#pragma unroll
        for (int h = 0; h < 2; h++) { m_i[mt][h] = -1e30f; l_i[mt][h] = 0.0f; }
#pragma unroll
    for (int mt = 0; mt < 2; mt++)
#pragma unroll
        for (int dt = 0; dt < 16; dt++)
#pragma unroll
            for (int c = 0; c < 4; c++) o[mt][dt][c] = 0.0f;

    for (int kt = 0; kt < SEQ / 128; kt++) {
        const int j0 = kt * 128;
        __syncthreads();  // previous iteration's smem reads complete
        // load K/V tiles (hi+lo): 128 rows x 16 uint4 each tensor
#pragma unroll
        for (int i = 0; i < 8; i++) {
            int id = tid + i * 256;
            int row = id >> 4, c4 = id & 15;
            uint32_t so = (uint32_t)(row * ATT_STR + c4 * 16);
            size_t go = (size_t)(j0 + row) * 16 + c4;
            *(uint4*)(sm + AKH + so) = ((const uint4*)g_Kh)[go];
            *(uint4*)(sm + AKL + so) = ((const uint4*)g_Kl)[go];
            *(uint4*)(sm + AVH + so) = ((const uint4*)g_Vh)[go];
            *(uint4*)(sm + AVL + so) = ((const uint4*)g_Vl)[go];
        }
        __syncthreads();

        // ---- S = Q K^T over this warp's n32 slice ----
        float s[2][4][4];
#pragma unroll
        for (int mt = 0; mt < 2; mt++)
#pragma unroll
            for (int nt = 0; nt < 4; nt++)
#pragma unroll
                for (int c = 0; c < 4; c++) s[mt][nt][c] = 0.0f;

#pragma unroll
        for (int kk = 0; kk < 8; kk++) {
            uint32_t ah[2][4], al[2][4];
#pragma unroll
            for (int mt = 0; mt < 2; mt++) {
                ldsm_a(ah[mt], sb + AQH, ATT_STR, warpM * 32 + mt * 16, kk * 16, lane);
                ldsm_a(al[mt], sb + AQL, ATT_STR, warpM * 32 + mt * 16, kk * 16, lane);
            }
            uint32_t bh[2][4], bl[2][4];
#pragma unroll
            for (int np = 0; np < 2; np++) {
                ldsm_bk(bh[np], sb + AKH, ATT_STR, warpN * 32 + np * 16, kk * 16, lane);
                ldsm_bk(bl[np], sb + AKL, ATT_STR, warpN * 32 + np * 16, kk * 16, lane);
            }
#pragma unroll
            for (int mt = 0; mt < 2; mt++)
#pragma unroll
                for (int nt = 0; nt < 4; nt++) {
                    const uint32_t* bhp = &bh[nt >> 1][(nt & 1) * 2];
                    const uint32_t* blp = &bl[nt >> 1][(nt & 1) * 2];
                    mma_bf16(s[mt][nt], ah[mt], bhp);
                    mma_bf16(s[mt][nt], ah[mt], blp);
                    mma_bf16(s[mt][nt], al[mt], bhp);
                }
        }

        // ---- online softmax ----
        float rmax[2][2];
#pragma unroll
        for (int mt = 0; mt < 2; mt++)
#pragma unroll
            for (int h = 0; h < 2; h++) {
                float m = -1e30f;
#pragma unroll
                for (int nt = 0; nt < 4; nt++)
                    m = fmaxf(m, fmaxf(s[mt][nt][h * 2], s[mt][nt][h * 2 + 1]));
                m = fmaxf(m, __shfl_xor_sync(0xffffffffu, m, 1));
                m = fmaxf(m, __shfl_xor_sync(0xffffffffu, m, 2));
                rmax[mt][h] = m;
            }
        if (q4 == 0) {
#pragma unroll
            for (int mt = 0; mt < 2; mt++)
#pragma unroll
                for (int h = 0; h < 2; h++)
                    redMax[warpN * 64 + warpM * 32 + mt * 16 + qr + h * 8] = rmax[mt][h];
        }
        __syncthreads();

        float alpha[2][2];
#pragma unroll
        for (int mt = 0; mt < 2; mt++)
#pragma unroll
            for (int h = 0; h < 2; h++) {
                int R = warpM * 32 + mt * 16 + qr + h * 8;
                float mn = fmaxf(fmaxf(redMax[R], redMax[64 + R]),
                                 fmaxf(redMax[128 + R], redMax[192 + R]));
                mn = fmaxf(m_i[mt][h], mn);
                alpha[mt][h] = __expf(m_i[mt][h] - mn);
                m_i[mt][h] = mn;
                float rs = 0.0f;
#pragma unroll
                for (int nt = 0; nt < 4; nt++) {
                    float p0 = __expf(s[mt][nt][h * 2]     - mn);
                    float p1 = __expf(s[mt][nt][h * 2 + 1] - mn);
                    s[mt][nt][h * 2]     = p0;
                    s[mt][nt][h * 2 + 1] = p1;
                    rs += p0 + p1;
                }
                rs += __shfl_xor_sync(0xffffffffu, rs, 1);
                rs += __shfl_xor_sync(0xffffffffu, rs, 2);
                if (q4 == 0) redSum[warpN * 64 + R] = rs;
            }
        __syncthreads();
#pragma unroll
        for (int mt = 0; mt < 2; mt++)
#pragma unroll
            for (int h = 0; h < 2; h++) {
                int R = warpM * 32 + mt * 16 + qr + h * 8;
                float rs = redSum[R] + redSum[64 + R] + redSum[128 + R] + redSum[192 + R];
                l_i[mt][h] = l_i[mt][h] * alpha[mt][h] + rs;
            }
        // rescale O
#pragma unroll
        for (int mt = 0; mt < 2; mt++)
#pragma unroll
            for (int dt = 0; dt < 16; dt++) {
                o[mt][dt][0] *= alpha[mt][0];
                o[mt][dt][1] *= alpha[mt][0];
                o[mt][dt][2] *= alpha[mt][1];
                o[mt][dt][3] *= alpha[mt][1];
            }

        // ---- PV over this warp's 32-key slice ----
#pragma unroll
        for (int ks = 0; ks < 2; ks++) {
            uint32_t ph[2][4], pl[2][4];
#pragma unroll
            for (int mt = 0; mt < 2; mt++) {
                split_pair(s[mt][2 * ks][0], s[mt][2 * ks][1], ph[mt][0], pl[mt][0]);
                split_pair(s[mt][2 * ks][2], s[mt][2 * ks][3], ph[mt][1], pl[mt][1]);
                split_pair(s[mt][2 * ks + 1][0], s[mt][2 * ks + 1][1], ph[mt][2], pl[mt][2]);
                split_pair(s[mt][2 * ks + 1][2], s[mt][2 * ks + 1][3], ph[mt][3], pl[mt][3]);
            }
            const int k_off = warpN * 32 + ks * 16;
#pragma unroll
            for (int dp = 0; dp < 8; dp++) {
                uint32_t bvh[4], bvl[4];
                ldsm_bv(bvh, sb + AVH, ATT_STR, k_off, dp * 16, lane);
                ldsm_bv(bvl, sb + AVL, ATT_STR, k_off, dp * 16, lane);
#pragma unroll
                for (int mt = 0; mt < 2; mt++)
#pragma unroll
                    for (int j = 0; j < 2; j++) {
                        mma_bf16(o[mt][2 * dp + j], ph[mt], &bvh[j * 2]);
                        mma_bf16(o[mt][2 * dp + j], ph[mt], &bvl[j * 2]);
                        mma_bf16(o[mt][2 * dp + j], pl[mt], &bvh[j * 2]);
                    }
            }
        }
    }

    // ---- reduce O across the 4 warpN groups via staging (aliases K tile) ----
    float* stage = (float*)(sm + AKH);  // [64][132]
    if (warpN == 0 && q4 == 0) {
#pragma unroll
        for (int mt = 0; mt < 2; mt++)
#pragma unroll
            for (int h = 0; h < 2; h++)
                linv[warpM * 32 + mt * 16 + qr + h * 8] = 1.0f / l_i[mt][h];
    }
    for (int wn = 0; wn < 4; wn++) {
        __syncthreads();
        if (warpN == wn) {
#pragma unroll
            for (int mt = 0; mt < 2; mt++)
#pragma unroll
                for (int h = 0; h < 2; h++) {
                    int R = warpM * 32 + mt * 16 + qr + h * 8;
#pragma unroll
                    for (int dt = 0; dt < 16; dt++) {
                        int col = dt * 8 + q4 * 2;
                        if (wn == 0) {
                            stage[R * 132 + col]     = o[mt][dt][h * 2];
                            stage[R * 132 + col + 1] = o[mt][dt][h * 2 + 1];
                        } else {
                            stage[R * 132 + col]     += o[mt][dt][h * 2];
                            stage[R * 132 + col + 1] += o[mt][dt][h * 2 + 1];
                        }
                    }
                }
        }
    }
    __syncthreads();

    // normalize + write
    {
        int row = tid >> 2;
        int cg = (tid & 3) * 32;
        float il = linv[row];
#pragma unroll
        for (int i = 0; i < 8; i++) {
            int col = cg + i * 4;
            float4 v = *(float4*)&stage[row * 132 + col];
            v.x *= il; v.y *= il; v.z *= il; v.w *= il;
            *(float4*)&out[(size_t)(qBase + row) * DK + col] = v;
        }
    }
}

// ---------------------------------------------------------------------------
extern "C" void kernel_launch(void* const* d_in, const int* in_sizes, int n_in,
                              void* d_out, int out_size)
{
    const float* x  = (const float*)d_in[0];
    const float* Wq = (const float*)d_in[1];
    const float* bq = (const float*)d_in[2];
    const float* Wk = (const float*)d_in[3];
    const float* bk = (const float*)d_in[4];
    const float* Wv = (const float*)d_in[5];
    const float* bv = (const float*)d_in[6];
    float* out = (float*)d_out;

    cudaFuncSetAttribute(proj_kernel, cudaFuncAttributeMaxDynamicSharedMemorySize, PRJ_SMEM);
    cudaFuncSetAttribute(attn_kernel, cudaFuncAttributeMaxDynamicSharedMemorySize, ATT_SMEM);

    dim3 gProj(SEQ / 128, 3);
    proj_kernel<<<gProj, 256, PRJ_SMEM>>>(x, Wq, bq, Wk, bk, Wv, bv);
    attn_kernel<<<SEQ / 64, 256, ATT_SMEM>>>(out);
}